// round 1
// baseline (speedup 1.0000x reference)
#include <cuda_runtime.h>
#include <math.h>

#define NMAX 50000
#define EMAX 600000
#define HDIM 128
#define NHEADS 4
#define GMAX 64

// ---------------- scratch (device globals; no allocation) ----------------
__device__ float d_h[NMAX * HDIM];
__device__ float d_feat[NMAX * HDIM];
__device__ float d_rst[NMAX * HDIM];
__device__ float d_el[NMAX * NHEADS];
__device__ float d_er[NMAX * NHEADS];
__device__ float d_mx[NMAX * NHEADS];
__device__ float d_zz[NMAX * NHEADS];
__device__ float d_a[EMAX * NHEADS];
__device__ float d_gate[NMAX];
__device__ float d_gmax[GMAX];
__device__ float d_gz[GMAX];
__device__ float d_zg[GMAX * HDIM];
__device__ float d_z1[GMAX * HDIM];

// ---------------- helpers ----------------
__device__ __forceinline__ void atomicMaxFloat(float* addr, float v) {
    // sign-aware float max via int/uint atomics (init must be -inf)
    if (v >= 0.0f) {
        atomicMax((int*)addr, __float_as_int(v));
    } else {
        atomicMin((unsigned int*)addr, __float_as_uint(v));
    }
}

__device__ __forceinline__ void redAdd4(float* p, float a, float b, float c, float d) {
    asm volatile("red.global.add.v4.f32 [%0], {%1, %2, %3, %4};"
                 :: "l"(p), "f"(a), "f"(b), "f"(c), "f"(d) : "memory");
}

__device__ __forceinline__ float warpSum(float v) {
    #pragma unroll
    for (int o = 16; o > 0; o >>= 1) v += __shfl_xor_sync(0xffffffffu, v, o);
    return v;
}

// ---------------- kernels ----------------

// h = gate_emb[gate_types] + qubit_emb[qubit_indices]
__global__ void embed_k(const int* __restrict__ gt, const int* __restrict__ qi,
                        const float* __restrict__ ge, const float* __restrict__ qe, int n) {
    int i = blockIdx.x * blockDim.x + threadIdx.x;
    if (i >= n * (HDIM / 4)) return;
    int node = i >> 5;
    int c = (i & 31) << 2;
    int g = gt[node], q = qi[node];
    float4 a = *(const float4*)(ge + g * HDIM + c);
    float4 b = *(const float4*)(qe + q * HDIM + c);
    float4 r;
    r.x = a.x + b.x; r.y = a.y + b.y; r.z = a.z + b.z; r.w = a.w + b.w;
    *(float4*)(d_h + node * HDIM + c) = r;
}

// per-layer reset of accumulators
__global__ void init_layer_k(int n) {
    int i = blockIdx.x * blockDim.x + threadIdx.x;
    if (i < n * HDIM) d_rst[i] = 0.0f;
    if (i < n * NHEADS) { d_mx[i] = -INFINITY; d_zz[i] = 0.0f; }
}

// feat = h @ W[l]   (A = d_h [n,128], B [128,128], C = d_feat)
__global__ void gemm128_k(const float* __restrict__ B, int n) {
    __shared__ float As[32][HDIM];
    int row0 = blockIdx.x * 32;
    int tid = threadIdx.x;  // 128 threads; tid = output column
    for (int j = tid; j < 32 * HDIM; j += 128) {
        int r = j >> 7, c = j & 127;
        As[r][c] = (row0 + r < n) ? d_h[(row0 + r) * HDIM + c] : 0.0f;
    }
    __syncthreads();
    float acc[32];
    #pragma unroll
    for (int r = 0; r < 32; r++) acc[r] = 0.0f;
    #pragma unroll 8
    for (int k = 0; k < HDIM; k++) {
        float b = B[k * HDIM + tid];
        #pragma unroll
        for (int r = 0; r < 32; r++) acc[r] += As[r][k] * b;
    }
    #pragma unroll
    for (int r = 0; r < 32; r++) {
        int row = row0 + r;
        if (row < n) d_feat[row * HDIM + tid] = acc[r];
    }
}

// el[n,h] = <feat[n,h,:], attn_l[h,:]>, same for er. One warp per node.
__global__ void attn_k(const float* __restrict__ al, const float* __restrict__ ar, int n) {
    int t = blockIdx.x * blockDim.x + threadIdx.x;
    int node = t >> 5;
    if (node >= n) return;
    int lane = t & 31;
    const float* f = d_feat + node * HDIM;
    #pragma unroll
    for (int hd = 0; hd < NHEADS; hd++) {
        float v = f[hd * 32 + lane];
        float sl = warpSum(v * al[hd * 32 + lane]);
        float sr = warpSum(v * ar[hd * 32 + lane]);
        if (lane == 0) {
            d_el[node * NHEADS + hd] = sl;
            d_er[node * NHEADS + hd] = sr;
        }
    }
}

// pass 1: per-(dst,head) max of leaky_relu(el[src]+er[dst])
__global__ void edge_max_k(const int* __restrict__ src, const int* __restrict__ dst, int e) {
    int i = blockIdx.x * blockDim.x + threadIdx.x;
    if (i >= e * NHEADS) return;
    int ed = i >> 2, hd = i & 3;
    int s = src[ed], d = dst[ed];
    float v = d_el[s * NHEADS + hd] + d_er[d * NHEADS + hd];
    v = (v > 0.0f) ? v : 0.2f * v;
    atomicMaxFloat(&d_mx[d * NHEADS + hd], v);
}

// pass 2: unnormalized exp + denominator sum
__global__ void edge_exp_k(const int* __restrict__ src, const int* __restrict__ dst, int e) {
    int i = blockIdx.x * blockDim.x + threadIdx.x;
    if (i >= e * NHEADS) return;
    int ed = i >> 2, hd = i & 3;
    int s = src[ed], d = dst[ed];
    float v = d_el[s * NHEADS + hd] + d_er[d * NHEADS + hd];
    v = (v > 0.0f) ? v : 0.2f * v;
    float a = expf(v - d_mx[d * NHEADS + hd]);
    d_a[i] = a;
    atomicAdd(&d_zz[d * NHEADS + hd], a);
}

// pass 3: rst[dst] += a_un[e] * feat[src]   (one warp per edge, vectorized RED)
__global__ void edge_aggr_k(const int* __restrict__ src, const int* __restrict__ dst, int e) {
    int t = blockIdx.x * blockDim.x + threadIdx.x;
    int ed = t >> 5;
    if (ed >= e) return;
    int lane = t & 31;
    int s = src[ed], d = dst[ed];
    float a = d_a[ed * NHEADS + (lane >> 3)];
    float4 f = *(const float4*)(d_feat + s * HDIM + lane * 4);
    redAdd4(d_rst + d * HDIM + lane * 4, f.x * a, f.y * a, f.z * a, f.w * a);
}

// h = relu(rst/z + h + bias)
__global__ void update_k(const float* __restrict__ bias, int n) {
    int i = blockIdx.x * blockDim.x + threadIdx.x;
    if (i >= n * HDIM) return;
    int c = i & 127, hd = c >> 5, node = i >> 7;
    float zv = d_zz[node * NHEADS + hd];
    float r = (zv > 0.0f) ? d_rst[i] / zv : 0.0f;
    float v = r + d_h[i] + bias[c];
    d_h[i] = (v > 0.0f) ? v : 0.0f;
}

// LayerNorm over 128, one warp per node, in-place on d_h
__global__ void ln_k(const float* __restrict__ gamma, const float* __restrict__ beta, int n) {
    int t = blockIdx.x * blockDim.x + threadIdx.x;
    int node = t >> 5;
    if (node >= n) return;
    int lane = t & 31;
    float4 x = *(const float4*)(d_h + node * HDIM + lane * 4);
    float s = x.x + x.y + x.z + x.w;
    float sq = x.x * x.x + x.y * x.y + x.z * x.z + x.w * x.w;
    s = warpSum(s);
    sq = warpSum(sq);
    float mu = s * (1.0f / HDIM);
    float var = sq * (1.0f / HDIM) - mu * mu;
    float inv = rsqrtf(var + 1e-5f);
    float4 g = *(const float4*)(gamma + lane * 4);
    float4 b = *(const float4*)(beta + lane * 4);
    float4 y;
    y.x = (x.x - mu) * inv * g.x + b.x;
    y.y = (x.y - mu) * inv * g.y + b.y;
    y.z = (x.z - mu) * inv * g.z + b.z;
    y.w = (x.w - mu) * inv * g.w + b.w;
    *(float4*)(d_h + node * HDIM + lane * 4) = y;
}

__global__ void pool_init_k() {
    int i = blockIdx.x * blockDim.x + threadIdx.x;
    if (i < GMAX * HDIM) d_zg[i] = 0.0f;
    if (i < GMAX) { d_gmax[i] = -INFINITY; d_gz[i] = 0.0f; }
}

// gate[n] = <h[n], gate_w> + gate_b, plus per-graph max. One warp per node.
__global__ void gate_k(const float* __restrict__ gw, const float* __restrict__ gb,
                       const int* __restrict__ gid, int n) {
    int t = blockIdx.x * blockDim.x + threadIdx.x;
    int node = t >> 5;
    if (node >= n) return;
    int lane = t & 31;
    float4 x = *(const float4*)(d_h + node * HDIM + lane * 4);
    float4 w = *(const float4*)(gw + lane * 4);
    float s = x.x * w.x + x.y * w.y + x.z * w.z + x.w * w.w;
    s = warpSum(s);
    if (lane == 0) {
        float g = s + gb[0];
        d_gate[node] = g;
        atomicMaxFloat(&d_gmax[gid[node]], g);
    }
}

// pool: p = exp(gate - gmax); gz += p; zg += p*h. One warp per node.
__global__ void pool_k(const int* __restrict__ gid, int n) {
    int t = blockIdx.x * blockDim.x + threadIdx.x;
    int node = t >> 5;
    if (node >= n) return;
    int lane = t & 31;
    int g = gid[node];
    float p = expf(d_gate[node] - d_gmax[g]);
    if (lane == 0) atomicAdd(&d_gz[g], p);
    float4 x = *(const float4*)(d_h + node * HDIM + lane * 4);
    redAdd4(d_zg + g * HDIM + lane * 4, x.x * p, x.y * p, x.z * p, x.w * p);
}

// z1 = relu((zg/gz) @ proj_w1 + b1). One block per graph, 128 threads.
__global__ void final1_k(const float* __restrict__ W1, const float* __restrict__ b1) {
    __shared__ float row[HDIM];
    int g = blockIdx.x;
    int t = threadIdx.x;
    float gz = d_gz[g];
    float inv = (gz > 0.0f) ? (1.0f / gz) : 0.0f;
    row[t] = d_zg[g * HDIM + t] * inv;
    __syncthreads();
    float acc = b1[t];
    #pragma unroll 8
    for (int k = 0; k < HDIM; k++) acc += row[k] * W1[k * HDIM + t];
    d_z1[g * HDIM + t] = (acc > 0.0f) ? acc : 0.0f;
}

// out = z1 @ proj_w2 + b2. One block per graph, 64 threads.
__global__ void final2_k(const float* __restrict__ W2, const float* __restrict__ b2,
                         float* __restrict__ out) {
    __shared__ float row[HDIM];
    int g = blockIdx.x;
    int t = threadIdx.x;
    row[t] = d_z1[g * HDIM + t];
    row[t + 64] = d_z1[g * HDIM + t + 64];
    __syncthreads();
    float acc = b2[t];
    #pragma unroll 8
    for (int k = 0; k < HDIM; k++) acc += row[k] * W2[k * 64 + t];
    out[g * 64 + t] = acc;
}

// ---------------- launch ----------------
extern "C" void kernel_launch(void* const* d_in, const int* in_sizes, int n_in,
                              void* d_out, int out_size) {
    const int*   gt    = (const int*)d_in[0];
    const int*   qi    = (const int*)d_in[1];
    const int*   src   = (const int*)d_in[2];
    const int*   dst   = (const int*)d_in[3];
    const int*   gid   = (const int*)d_in[4];
    const float* ge    = (const float*)d_in[5];
    const float* qe    = (const float*)d_in[6];
    const float* W     = (const float*)d_in[7];
    const float* al    = (const float*)d_in[8];
    const float* ar    = (const float*)d_in[9];
    const float* bias  = (const float*)d_in[10];
    const float* gamma = (const float*)d_in[11];
    const float* beta  = (const float*)d_in[12];
    const float* gw    = (const float*)d_in[13];
    const float* gb    = (const float*)d_in[14];
    const float* W1    = (const float*)d_in[15];
    const float* b1    = (const float*)d_in[16];
    const float* W2    = (const float*)d_in[17];
    const float* b2    = (const float*)d_in[18];

    int n = in_sizes[0];
    int e = in_sizes[2];

    const int T = 256;
    int gEmbed = (n * (HDIM / 4) + T - 1) / T;
    int gInit  = (n * HDIM + T - 1) / T;
    int gGemm  = (n + 31) / 32;
    int gWarpN = (n * 32 + T - 1) / T;   // one warp per node
    int gEdgeH = (e * NHEADS + T - 1) / T;
    int gEdgeW = (e * 32 + T - 1) / T;   // one warp per edge

    embed_k<<<gEmbed, T>>>(gt, qi, ge, qe, n);

    for (int l = 0; l < 3; l++) {
        init_layer_k<<<gInit, T>>>(n);
        gemm128_k<<<gGemm, 128>>>(W + l * HDIM * HDIM, n);
        attn_k<<<gWarpN, T>>>(al + l * HDIM, ar + l * HDIM, n);
        edge_max_k<<<gEdgeH, T>>>(src, dst, e);
        edge_exp_k<<<gEdgeH, T>>>(src, dst, e);
        edge_aggr_k<<<gEdgeW, T>>>(src, dst, e);
        update_k<<<gInit, T>>>(bias + l * HDIM, n);
    }

    ln_k<<<gWarpN, T>>>(gamma, beta, n);
    pool_init_k<<<(GMAX * HDIM + T - 1) / T, T>>>();
    gate_k<<<gWarpN, T>>>(gw, gb, gid, n);
    pool_k<<<gWarpN, T>>>(gid, n);
    final1_k<<<GMAX, HDIM>>>(W1, b1);
    final2_k<<<GMAX, 64>>>(W2, b2, (float*)d_out);
}

// round 2
// speedup vs baseline: 1.0000x; 1.0000x over previous
#include <cuda_runtime.h>
#include <math.h>

#define NMAX 50000
#define EMAX 600000
#define HDIM 128
#define NHEADS 4
#define GMAX 64

// ---------------- scratch (device globals; no allocation) ----------------
__device__ float d_h[NMAX * HDIM];
__device__ float d_feat[NMAX * HDIM];
__device__ float d_rst[NMAX * HDIM];
__device__ float d_el[NMAX * NHEADS];
__device__ float d_er[NMAX * NHEADS];
__device__ float d_mx[NMAX * NHEADS];
__device__ float d_zz[NMAX * NHEADS];
__device__ float d_a[EMAX * NHEADS];
__device__ float d_gate[NMAX];
__device__ float d_gmax[GMAX];
__device__ float d_gz[GMAX];
__device__ float d_zg[GMAX * HDIM];
__device__ float d_z1[GMAX * HDIM];

// ---------------- helpers ----------------
__device__ __forceinline__ void atomicMaxFloat(float* addr, float v) {
    // sign-aware float max via int/uint atomics (init must be -inf)
    if (v >= 0.0f) {
        atomicMax((int*)addr, __float_as_int(v));
    } else {
        atomicMin((unsigned int*)addr, __float_as_uint(v));
    }
}

__device__ __forceinline__ void redAdd4(float* p, float a, float b, float c, float d) {
    asm volatile("red.global.add.v4.f32 [%0], {%1, %2, %3, %4};"
                 :: "l"(p), "f"(a), "f"(b), "f"(c), "f"(d) : "memory");
}

__device__ __forceinline__ float warpSum(float v) {
    #pragma unroll
    for (int o = 16; o > 0; o >>= 1) v += __shfl_xor_sync(0xffffffffu, v, o);
    return v;
}

// ---------------- kernels ----------------

// h = gate_emb[gate_types] + qubit_emb[qubit_indices]
__global__ void embed_k(const int* __restrict__ gt, const int* __restrict__ qi,
                        const float* __restrict__ ge, const float* __restrict__ qe, int n) {
    int i = blockIdx.x * blockDim.x + threadIdx.x;
    if (i >= n * (HDIM / 4)) return;
    int node = i >> 5;
    int c = (i & 31) << 2;
    int g = gt[node], q = qi[node];
    float4 a = *(const float4*)(ge + g * HDIM + c);
    float4 b = *(const float4*)(qe + q * HDIM + c);
    float4 r;
    r.x = a.x + b.x; r.y = a.y + b.y; r.z = a.z + b.z; r.w = a.w + b.w;
    *(float4*)(d_h + node * HDIM + c) = r;
}

// per-layer reset of accumulators
__global__ void init_layer_k(int n) {
    int i = blockIdx.x * blockDim.x + threadIdx.x;
    if (i < n * HDIM) d_rst[i] = 0.0f;
    if (i < n * NHEADS) { d_mx[i] = -INFINITY; d_zz[i] = 0.0f; }
}

// feat = h @ W[l]   (A = d_h [n,128], B [128,128], C = d_feat)
__global__ void gemm128_k(const float* __restrict__ B, int n) {
    __shared__ float As[32][HDIM];
    int row0 = blockIdx.x * 32;
    int tid = threadIdx.x;  // 128 threads; tid = output column
    for (int j = tid; j < 32 * HDIM; j += 128) {
        int r = j >> 7, c = j & 127;
        As[r][c] = (row0 + r < n) ? d_h[(row0 + r) * HDIM + c] : 0.0f;
    }
    __syncthreads();
    float acc[32];
    #pragma unroll
    for (int r = 0; r < 32; r++) acc[r] = 0.0f;
    #pragma unroll 8
    for (int k = 0; k < HDIM; k++) {
        float b = B[k * HDIM + tid];
        #pragma unroll
        for (int r = 0; r < 32; r++) acc[r] += As[r][k] * b;
    }
    #pragma unroll
    for (int r = 0; r < 32; r++) {
        int row = row0 + r;
        if (row < n) d_feat[row * HDIM + tid] = acc[r];
    }
}

// el[n,h] = <feat[n,h,:], attn_l[h,:]>, same for er. One warp per node.
__global__ void attn_k(const float* __restrict__ al, const float* __restrict__ ar, int n) {
    int t = blockIdx.x * blockDim.x + threadIdx.x;
    int node = t >> 5;
    if (node >= n) return;
    int lane = t & 31;
    const float* f = d_feat + node * HDIM;
    #pragma unroll
    for (int hd = 0; hd < NHEADS; hd++) {
        float v = f[hd * 32 + lane];
        float sl = warpSum(v * al[hd * 32 + lane]);
        float sr = warpSum(v * ar[hd * 32 + lane]);
        if (lane == 0) {
            d_el[node * NHEADS + hd] = sl;
            d_er[node * NHEADS + hd] = sr;
        }
    }
}

// pass 1: per-(dst,head) max of leaky_relu(el[src]+er[dst])
__global__ void edge_max_k(const int* __restrict__ src, const int* __restrict__ dst, int e) {
    int i = blockIdx.x * blockDim.x + threadIdx.x;
    if (i >= e * NHEADS) return;
    int ed = i >> 2, hd = i & 3;
    int s = src[ed], d = dst[ed];
    float v = d_el[s * NHEADS + hd] + d_er[d * NHEADS + hd];
    v = (v > 0.0f) ? v : 0.2f * v;
    atomicMaxFloat(&d_mx[d * NHEADS + hd], v);
}

// pass 2: unnormalized exp + denominator sum
__global__ void edge_exp_k(const int* __restrict__ src, const int* __restrict__ dst, int e) {
    int i = blockIdx.x * blockDim.x + threadIdx.x;
    if (i >= e * NHEADS) return;
    int ed = i >> 2, hd = i & 3;
    int s = src[ed], d = dst[ed];
    float v = d_el[s * NHEADS + hd] + d_er[d * NHEADS + hd];
    v = (v > 0.0f) ? v : 0.2f * v;
    float a = expf(v - d_mx[d * NHEADS + hd]);
    d_a[i] = a;
    atomicAdd(&d_zz[d * NHEADS + hd], a);
}

// pass 3: rst[dst] += a_un[e] * feat[src]   (one warp per edge, vectorized RED)
__global__ void edge_aggr_k(const int* __restrict__ src, const int* __restrict__ dst, int e) {
    int t = blockIdx.x * blockDim.x + threadIdx.x;
    int ed = t >> 5;
    if (ed >= e) return;
    int lane = t & 31;
    int s = src[ed], d = dst[ed];
    float a = d_a[ed * NHEADS + (lane >> 3)];
    float4 f = *(const float4*)(d_feat + s * HDIM + lane * 4);
    redAdd4(d_rst + d * HDIM + lane * 4, f.x * a, f.y * a, f.z * a, f.w * a);
}

// h = relu(rst/z + h + bias)
__global__ void update_k(const float* __restrict__ bias, int n) {
    int i = blockIdx.x * blockDim.x + threadIdx.x;
    if (i >= n * HDIM) return;
    int c = i & 127, hd = c >> 5, node = i >> 7;
    float zv = d_zz[node * NHEADS + hd];
    float r = (zv > 0.0f) ? d_rst[i] / zv : 0.0f;
    float v = r + d_h[i] + bias[c];
    d_h[i] = (v > 0.0f) ? v : 0.0f;
}

// LayerNorm over 128, one warp per node, in-place on d_h
__global__ void ln_k(const float* __restrict__ gamma, const float* __restrict__ beta, int n) {
    int t = blockIdx.x * blockDim.x + threadIdx.x;
    int node = t >> 5;
    if (node >= n) return;
    int lane = t & 31;
    float4 x = *(const float4*)(d_h + node * HDIM + lane * 4);
    float s = x.x + x.y + x.z + x.w;
    float sq = x.x * x.x + x.y * x.y + x.z * x.z + x.w * x.w;
    s = warpSum(s);
    sq = warpSum(sq);
    float mu = s * (1.0f / HDIM);
    float var = sq * (1.0f / HDIM) - mu * mu;
    float inv = rsqrtf(var + 1e-5f);
    float4 g = *(const float4*)(gamma + lane * 4);
    float4 b = *(const float4*)(beta + lane * 4);
    float4 y;
    y.x = (x.x - mu) * inv * g.x + b.x;
    y.y = (x.y - mu) * inv * g.y + b.y;
    y.z = (x.z - mu) * inv * g.z + b.z;
    y.w = (x.w - mu) * inv * g.w + b.w;
    *(float4*)(d_h + node * HDIM + lane * 4) = y;
}

__global__ void pool_init_k() {
    int i = blockIdx.x * blockDim.x + threadIdx.x;
    if (i < GMAX * HDIM) d_zg[i] = 0.0f;
    if (i < GMAX) { d_gmax[i] = -INFINITY; d_gz[i] = 0.0f; }
}

// gate[n] = <h[n], gate_w> + gate_b, plus per-graph max. One warp per node.
__global__ void gate_k(const float* __restrict__ gw, const float* __restrict__ gb,
                       const int* __restrict__ gid, int n) {
    int t = blockIdx.x * blockDim.x + threadIdx.x;
    int node = t >> 5;
    if (node >= n) return;
    int lane = t & 31;
    float4 x = *(const float4*)(d_h + node * HDIM + lane * 4);
    float4 w = *(const float4*)(gw + lane * 4);
    float s = x.x * w.x + x.y * w.y + x.z * w.z + x.w * w.w;
    s = warpSum(s);
    if (lane == 0) {
        float g = s + gb[0];
        d_gate[node] = g;
        atomicMaxFloat(&d_gmax[gid[node]], g);
    }
}

// pool: p = exp(gate - gmax); gz += p; zg += p*h. One warp per node.
__global__ void pool_k(const int* __restrict__ gid, int n) {
    int t = blockIdx.x * blockDim.x + threadIdx.x;
    int node = t >> 5;
    if (node >= n) return;
    int lane = t & 31;
    int g = gid[node];
    float p = expf(d_gate[node] - d_gmax[g]);
    if (lane == 0) atomicAdd(&d_gz[g], p);
    float4 x = *(const float4*)(d_h + node * HDIM + lane * 4);
    redAdd4(d_zg + g * HDIM + lane * 4, x.x * p, x.y * p, x.z * p, x.w * p);
}

// z1 = relu((zg/gz) @ proj_w1 + b1). One block per graph, 128 threads.
__global__ void final1_k(const float* __restrict__ W1, const float* __restrict__ b1) {
    __shared__ float row[HDIM];
    int g = blockIdx.x;
    int t = threadIdx.x;
    float gz = d_gz[g];
    float inv = (gz > 0.0f) ? (1.0f / gz) : 0.0f;
    row[t] = d_zg[g * HDIM + t] * inv;
    __syncthreads();
    float acc = b1[t];
    #pragma unroll 8
    for (int k = 0; k < HDIM; k++) acc += row[k] * W1[k * HDIM + t];
    d_z1[g * HDIM + t] = (acc > 0.0f) ? acc : 0.0f;
}

// out = z1 @ proj_w2 + b2. One block per graph, 64 threads.
__global__ void final2_k(const float* __restrict__ W2, const float* __restrict__ b2,
                         float* __restrict__ out) {
    __shared__ float row[HDIM];
    int g = blockIdx.x;
    int t = threadIdx.x;
    row[t] = d_z1[g * HDIM + t];
    row[t + 64] = d_z1[g * HDIM + t + 64];
    __syncthreads();
    float acc = b2[t];
    #pragma unroll 8
    for (int k = 0; k < HDIM; k++) acc += row[k] * W2[k * 64 + t];
    out[g * 64 + t] = acc;
}

// ---------------- launch ----------------
extern "C" void kernel_launch(void* const* d_in, const int* in_sizes, int n_in,
                              void* d_out, int out_size) {
    const int*   gt    = (const int*)d_in[0];
    const int*   qi    = (const int*)d_in[1];
    const int*   src   = (const int*)d_in[2];
    const int*   dst   = (const int*)d_in[3];
    const int*   gid   = (const int*)d_in[4];
    const float* ge    = (const float*)d_in[5];
    const float* qe    = (const float*)d_in[6];
    const float* W     = (const float*)d_in[7];
    const float* al    = (const float*)d_in[8];
    const float* ar    = (const float*)d_in[9];
    const float* bias  = (const float*)d_in[10];
    const float* gamma = (const float*)d_in[11];
    const float* beta  = (const float*)d_in[12];
    const float* gw    = (const float*)d_in[13];
    const float* gb    = (const float*)d_in[14];
    const float* W1    = (const float*)d_in[15];
    const float* b1    = (const float*)d_in[16];
    const float* W2    = (const float*)d_in[17];
    const float* b2    = (const float*)d_in[18];

    int n = in_sizes[0];
    int e = in_sizes[2];

    const int T = 256;
    int gEmbed = (n * (HDIM / 4) + T - 1) / T;
    int gInit  = (n * HDIM + T - 1) / T;
    int gGemm  = (n + 31) / 32;
    int gWarpN = (n * 32 + T - 1) / T;   // one warp per node
    int gEdgeH = (e * NHEADS + T - 1) / T;
    int gEdgeW = (e * 32 + T - 1) / T;   // one warp per edge

    embed_k<<<gEmbed, T>>>(gt, qi, ge, qe, n);

    for (int l = 0; l < 3; l++) {
        init_layer_k<<<gInit, T>>>(n);
        gemm128_k<<<gGemm, 128>>>(W + l * HDIM * HDIM, n);
        attn_k<<<gWarpN, T>>>(al + l * HDIM, ar + l * HDIM, n);
        edge_max_k<<<gEdgeH, T>>>(src, dst, e);
        edge_exp_k<<<gEdgeH, T>>>(src, dst, e);
        edge_aggr_k<<<gEdgeW, T>>>(src, dst, e);
        update_k<<<gInit, T>>>(bias + l * HDIM, n);
    }

    ln_k<<<gWarpN, T>>>(gamma, beta, n);
    pool_init_k<<<(GMAX * HDIM + T - 1) / T, T>>>();
    gate_k<<<gWarpN, T>>>(gw, gb, gid, n);
    pool_k<<<gWarpN, T>>>(gid, n);
    final1_k<<<GMAX, HDIM>>>(W1, b1);
    final2_k<<<GMAX, 64>>>(W2, b2, (float*)d_out);
}

// round 3
// speedup vs baseline: 1.3777x; 1.3776x over previous
#include <cuda_runtime.h>
#include <math.h>

#define NMAX 50000
#define EMAX 600000
#define HDIM 128
#define NHEADS 4
#define GMAX 64

// ---------------- scratch (device globals; no allocation) ----------------
__device__ float d_h[NMAX * HDIM];
__device__ float d_feat[NMAX * HDIM];
__device__ float d_el[NMAX * NHEADS];
__device__ float d_er[NMAX * NHEADS];
__device__ int   d_deg[NMAX];
__device__ int   d_cur[NMAX];
__device__ int   d_offs[NMAX + 1];
__device__ int   d_esrc[EMAX];
__device__ float d_gate[NMAX];
__device__ float d_gmax[GMAX];
__device__ float d_gz[GMAX];
__device__ float d_zg[GMAX * HDIM];
__device__ float d_z1[GMAX * HDIM];

// ---------------- helpers ----------------
__device__ __forceinline__ void atomicMaxFloat(float* addr, float v) {
    if (v >= 0.0f) atomicMax((int*)addr, __float_as_int(v));
    else           atomicMin((unsigned int*)addr, __float_as_uint(v));
}

__device__ __forceinline__ void redAdd4(float* p, float a, float b, float c, float d) {
    asm volatile("red.global.add.v4.f32 [%0], {%1, %2, %3, %4};"
                 :: "l"(p), "f"(a), "f"(b), "f"(c), "f"(d) : "memory");
}

__device__ __forceinline__ float warpSum(float v) {
    #pragma unroll
    for (int o = 16; o > 0; o >>= 1) v += __shfl_xor_sync(0xffffffffu, v, o);
    return v;
}

// ---------------- kernels ----------------

// h = gate_emb[gate_types] + qubit_emb[qubit_indices]
__global__ void embed_k(const int* __restrict__ gt, const int* __restrict__ qi,
                        const float* __restrict__ ge, const float* __restrict__ qe, int n) {
    int i = blockIdx.x * blockDim.x + threadIdx.x;
    if (i >= n * (HDIM / 4)) return;
    int node = i >> 5;
    int c = (i & 31) << 2;
    int g = gt[node], q = qi[node];
    float4 a = *(const float4*)(ge + g * HDIM + c);
    float4 b = *(const float4*)(qe + q * HDIM + c);
    float4 r;
    r.x = a.x + b.x; r.y = a.y + b.y; r.z = a.z + b.z; r.w = a.w + b.w;
    *(float4*)(d_h + node * HDIM + c) = r;
}

// --------- CSR build (once per call) ---------
__global__ void csr_zero_k(int n) {
    int i = blockIdx.x * blockDim.x + threadIdx.x;
    if (i < n) { d_deg[i] = 0; d_cur[i] = 0; }
}

__global__ void csr_hist_k(const int* __restrict__ dst, int e) {
    int i = blockIdx.x * blockDim.x + threadIdx.x;
    if (i < e) atomicAdd(&d_deg[dst[i]], 1);
}

// single-block exclusive scan over n counts (n <= 1024*chunk)
__global__ void csr_scan_k(int n) {
    __shared__ int sh[1024];
    int t = threadIdx.x;
    int chunk = (n + 1023) >> 10;
    int b = t * chunk;
    int e = min(b + chunk, n);
    int s = 0;
    for (int i = b; i < e; i++) s += d_deg[i];
    sh[t] = s;
    __syncthreads();
    #pragma unroll
    for (int off = 1; off < 1024; off <<= 1) {
        int v = (t >= off) ? sh[t - off] : 0;
        __syncthreads();
        sh[t] += v;
        __syncthreads();
    }
    int run = (t == 0) ? 0 : sh[t - 1];
    for (int i = b; i < e; i++) { d_offs[i] = run; run += d_deg[i]; }
    if (t == 1023) d_offs[n] = sh[1023];
}

__global__ void csr_scatter_k(const int* __restrict__ src, const int* __restrict__ dst, int e) {
    int i = blockIdx.x * blockDim.x + threadIdx.x;
    if (i >= e) return;
    int d = dst[i];
    int pos = d_offs[d] + atomicAdd(&d_cur[d], 1);
    d_esrc[pos] = src[i];
}

// feat = h @ W[l]
__global__ void gemm128_k(const float* __restrict__ B, int n) {
    __shared__ float As[32][HDIM];
    int row0 = blockIdx.x * 32;
    int tid = threadIdx.x;  // 128 threads; tid = output column
    for (int j = tid; j < 32 * HDIM; j += 128) {
        int r = j >> 7, c = j & 127;
        As[r][c] = (row0 + r < n) ? d_h[(row0 + r) * HDIM + c] : 0.0f;
    }
    __syncthreads();
    float acc[32];
    #pragma unroll
    for (int r = 0; r < 32; r++) acc[r] = 0.0f;
    #pragma unroll 8
    for (int k = 0; k < HDIM; k++) {
        float b = __ldg(B + k * HDIM + tid);
        #pragma unroll
        for (int r = 0; r < 32; r++) acc[r] += As[r][k] * b;
    }
    #pragma unroll
    for (int r = 0; r < 32; r++) {
        int row = row0 + r;
        if (row < n) d_feat[row * HDIM + tid] = acc[r];
    }
}

// el/er: warp per node, lane covers 4 floats, head = lane>>3, 8-lane segmented reduce
__global__ void attn_k(const float* __restrict__ al, const float* __restrict__ ar, int n) {
    int t = blockIdx.x * blockDim.x + threadIdx.x;
    int node = t >> 5;
    if (node >= n) return;
    int lane = t & 31;
    float4 f = *(const float4*)(d_feat + node * HDIM + lane * 4);
    float4 a = *(const float4*)(al + lane * 4);
    float4 r = *(const float4*)(ar + lane * 4);
    float sl = f.x * a.x + f.y * a.y + f.z * a.z + f.w * a.w;
    float sr = f.x * r.x + f.y * r.y + f.z * r.z + f.w * r.w;
    #pragma unroll
    for (int o = 4; o > 0; o >>= 1) {
        sl += __shfl_xor_sync(0xffffffffu, sl, o);
        sr += __shfl_xor_sync(0xffffffffu, sr, o);
    }
    if ((lane & 7) == 0) {
        int hd = lane >> 3;
        d_el[node * NHEADS + hd] = sl;
        d_er[node * NHEADS + hd] = sr;
    }
}

// Fused per-layer GAT aggregation: warp per dst node.
// Phase A: online softmax stats per head (no atomics).
// Phase B: accumulate a*feat[src] in registers, epilogue residual+bias+relu -> d_h.
__global__ void gat_fused_k(const float* __restrict__ bias, int n) {
    int warp = (blockIdx.x * blockDim.x + threadIdx.x) >> 5;
    if (warp >= n) return;
    int lane = threadIdx.x & 31;
    int node = warp;
    int rs = d_offs[node], re = d_offs[node + 1];
    int head = lane >> 3;

    float4 er4 = *(const float4*)(d_er + node * NHEADS);
    float erh[4] = {er4.x, er4.y, er4.z, er4.w};

    // Phase A: per-lane online softmax over strided edges
    float m[4], z[4];
    #pragma unroll
    for (int h = 0; h < 4; h++) { m[h] = -1e30f; z[h] = 0.0f; }
    for (int i = rs + lane; i < re; i += 32) {
        int s = d_esrc[i];
        float4 el4 = *(const float4*)(d_el + s * NHEADS);
        float ev[4] = {el4.x + er4.x, el4.y + er4.y, el4.z + er4.z, el4.w + er4.w};
        #pragma unroll
        for (int h = 0; h < 4; h++) {
            float v = ev[h];
            v = (v > 0.0f) ? v : 0.2f * v;
            float nm = fmaxf(m[h], v);
            z[h] = z[h] * __expf(m[h] - nm) + __expf(v - nm);
            m[h] = nm;
        }
    }
    // butterfly combine (all lanes end with full-warp stats)
    #pragma unroll
    for (int o = 16; o > 0; o >>= 1) {
        #pragma unroll
        for (int h = 0; h < 4; h++) {
            float om = __shfl_xor_sync(0xffffffffu, m[h], o);
            float oz = __shfl_xor_sync(0xffffffffu, z[h], o);
            float nm = fmaxf(m[h], om);
            z[h] = z[h] * __expf(m[h] - nm) + oz * __expf(om - nm);
            m[h] = nm;
        }
    }
    float m_h = m[head];
    float zq = z[head];
    float rz_h = (zq > 0.0f) ? (1.0f / zq) : 0.0f;
    float er_h = erh[head];

    // Phase B: joint loop over edges, lane owns 4 feature channels
    float4 acc = make_float4(0.0f, 0.0f, 0.0f, 0.0f);
    for (int i = rs; i < re; i++) {
        int s = d_esrc[i];                         // broadcast load
        float el_h = d_el[s * NHEADS + head];      // 4-way broadcast load
        float v = el_h + er_h;
        v = (v > 0.0f) ? v : 0.2f * v;
        float a = __expf(v - m_h) * rz_h;
        float4 f = *(const float4*)(d_feat + s * HDIM + lane * 4);
        acc.x += a * f.x; acc.y += a * f.y; acc.z += a * f.z; acc.w += a * f.w;
    }

    // epilogue: h = relu(rst + h + bias)
    float4 hv = *(const float4*)(d_h + node * HDIM + lane * 4);
    float4 bv = *(const float4*)(bias + lane * 4);
    float4 y;
    y.x = fmaxf(acc.x + hv.x + bv.x, 0.0f);
    y.y = fmaxf(acc.y + hv.y + bv.y, 0.0f);
    y.z = fmaxf(acc.z + hv.z + bv.z, 0.0f);
    y.w = fmaxf(acc.w + hv.w + bv.w, 0.0f);
    *(float4*)(d_h + node * HDIM + lane * 4) = y;
}

// Fused LayerNorm + gate projection + per-graph gate max. Warp per node, in-place on d_h.
__global__ void ln_gate_k(const float* __restrict__ gamma, const float* __restrict__ beta,
                          const float* __restrict__ gw, const float* __restrict__ gb,
                          const int* __restrict__ gid, int n) {
    int t = blockIdx.x * blockDim.x + threadIdx.x;
    int node = t >> 5;
    if (node >= n) return;
    int lane = t & 31;
    float4 x = *(const float4*)(d_h + node * HDIM + lane * 4);
    float s = x.x + x.y + x.z + x.w;
    float sq = x.x * x.x + x.y * x.y + x.z * x.z + x.w * x.w;
    s = warpSum(s);
    sq = warpSum(sq);
    float mu = s * (1.0f / HDIM);
    float var = sq * (1.0f / HDIM) - mu * mu;
    float inv = rsqrtf(var + 1e-5f);
    float4 g = *(const float4*)(gamma + lane * 4);
    float4 b = *(const float4*)(beta + lane * 4);
    float4 y;
    y.x = (x.x - mu) * inv * g.x + b.x;
    y.y = (x.y - mu) * inv * g.y + b.y;
    y.z = (x.z - mu) * inv * g.z + b.z;
    y.w = (x.w - mu) * inv * g.w + b.w;
    *(float4*)(d_h + node * HDIM + lane * 4) = y;
    // gate projection on normalized value
    float4 w = *(const float4*)(gw + lane * 4);
    float gp = y.x * w.x + y.y * w.y + y.z * w.z + y.w * w.w;
    gp = warpSum(gp);
    if (lane == 0) {
        float gv = gp + gb[0];
        d_gate[node] = gv;
        atomicMaxFloat(&d_gmax[gid[node]], gv);
    }
}

__global__ void pool_init_k() {
    int i = blockIdx.x * blockDim.x + threadIdx.x;
    if (i < GMAX * HDIM) d_zg[i] = 0.0f;
    if (i < GMAX) { d_gmax[i] = -INFINITY; d_gz[i] = 0.0f; }
}

// pool: p = exp(gate - gmax); gz += p; zg += p*h. One warp per node.
__global__ void pool_k(const int* __restrict__ gid, int n) {
    int t = blockIdx.x * blockDim.x + threadIdx.x;
    int node = t >> 5;
    if (node >= n) return;
    int lane = t & 31;
    int g = gid[node];
    float p = __expf(d_gate[node] - d_gmax[g]);
    if (lane == 0) atomicAdd(&d_gz[g], p);
    float4 x = *(const float4*)(d_h + node * HDIM + lane * 4);
    redAdd4(d_zg + g * HDIM + lane * 4, x.x * p, x.y * p, x.z * p, x.w * p);
}

// z1 = relu((zg/gz) @ proj_w1 + b1)
__global__ void final1_k(const float* __restrict__ W1, const float* __restrict__ b1) {
    __shared__ float row[HDIM];
    int g = blockIdx.x;
    int t = threadIdx.x;
    float gz = d_gz[g];
    float inv = (gz > 0.0f) ? (1.0f / gz) : 0.0f;
    row[t] = d_zg[g * HDIM + t] * inv;
    __syncthreads();
    float acc = b1[t];
    #pragma unroll 8
    for (int k = 0; k < HDIM; k++) acc += row[k] * W1[k * HDIM + t];
    d_z1[g * HDIM + t] = (acc > 0.0f) ? acc : 0.0f;
}

// out = z1 @ proj_w2 + b2
__global__ void final2_k(const float* __restrict__ W2, const float* __restrict__ b2,
                         float* __restrict__ out) {
    __shared__ float row[HDIM];
    int g = blockIdx.x;
    int t = threadIdx.x;
    row[t] = d_z1[g * HDIM + t];
    row[t + 64] = d_z1[g * HDIM + t + 64];
    __syncthreads();
    float acc = b2[t];
    #pragma unroll 8
    for (int k = 0; k < HDIM; k++) acc += row[k] * W2[k * 64 + t];
    out[g * 64 + t] = acc;
}

// ---------------- launch ----------------
extern "C" void kernel_launch(void* const* d_in, const int* in_sizes, int n_in,
                              void* d_out, int out_size) {
    const int*   gt    = (const int*)d_in[0];
    const int*   qi    = (const int*)d_in[1];
    const int*   src   = (const int*)d_in[2];
    const int*   dst   = (const int*)d_in[3];
    const int*   gid   = (const int*)d_in[4];
    const float* ge    = (const float*)d_in[5];
    const float* qe    = (const float*)d_in[6];
    const float* W     = (const float*)d_in[7];
    const float* al    = (const float*)d_in[8];
    const float* ar    = (const float*)d_in[9];
    const float* bias  = (const float*)d_in[10];
    const float* gamma = (const float*)d_in[11];
    const float* beta  = (const float*)d_in[12];
    const float* gw    = (const float*)d_in[13];
    const float* gb    = (const float*)d_in[14];
    const float* W1    = (const float*)d_in[15];
    const float* b1    = (const float*)d_in[16];
    const float* W2    = (const float*)d_in[17];
    const float* b2    = (const float*)d_in[18];

    int n = in_sizes[0];
    int e = in_sizes[2];

    const int T = 256;
    int gEmbed = (n * (HDIM / 4) + T - 1) / T;
    int gGemm  = (n + 31) / 32;
    int gWarpN = (n * 32 + T - 1) / T;   // one warp per node
    int gEdge  = (e + T - 1) / T;
    int gNode  = (n + T - 1) / T;

    embed_k<<<gEmbed, T>>>(gt, qi, ge, qe, n);

    // CSR build (once per call)
    csr_zero_k<<<gNode, T>>>(n);
    csr_hist_k<<<gEdge, T>>>(dst, e);
    csr_scan_k<<<1, 1024>>>(n);
    csr_scatter_k<<<gEdge, T>>>(src, dst, e);

    for (int l = 0; l < 3; l++) {
        gemm128_k<<<gGemm, 128>>>(W + l * HDIM * HDIM, n);
        attn_k<<<gWarpN, T>>>(al + l * HDIM, ar + l * HDIM, n);
        gat_fused_k<<<gWarpN, T>>>(bias + l * HDIM, n);
    }

    pool_init_k<<<(GMAX * HDIM + T - 1) / T, T>>>();
    ln_gate_k<<<gWarpN, T>>>(gamma, beta, gw, gb, gid, n);
    pool_k<<<gWarpN, T>>>(gid, n);
    final1_k<<<GMAX, HDIM>>>(W1, b1);
    final2_k<<<GMAX, 64>>>(W2, b2, (float*)d_out);
}

// round 4
// speedup vs baseline: 1.7613x; 1.2785x over previous
#include <cuda_runtime.h>
#include <math.h>

#define NMAX 50000
#define EMAX 600000
#define HDIM 128
#define NHEADS 4
#define GMAX 64

// ---------------- scratch (device globals; no allocation) ----------------
__device__ float d_h[NMAX * HDIM];
__device__ float d_feat[NMAX * HDIM];
__device__ float d_el[NMAX * NHEADS];
__device__ float d_er[NMAX * NHEADS];
__device__ int   d_deg[NMAX];
__device__ int   d_cur[NMAX];
__device__ int   d_offs[NMAX + 1];
__device__ int   d_esrc[EMAX];
__device__ int   d_bsum[64];
__device__ int   d_bbase[64];
__device__ float d_gate[NMAX];
__device__ float d_gmax[GMAX];
__device__ float d_gz[GMAX];
__device__ float d_zg[GMAX * HDIM];
__device__ float d_z1[GMAX * HDIM];

// ---------------- helpers ----------------
__device__ __forceinline__ void atomicMaxFloat(float* addr, float v) {
    if (v >= 0.0f) atomicMax((int*)addr, __float_as_int(v));
    else           atomicMin((unsigned int*)addr, __float_as_uint(v));
}

__device__ __forceinline__ void redAdd4(float* p, float a, float b, float c, float d) {
    asm volatile("red.global.add.v4.f32 [%0], {%1, %2, %3, %4};"
                 :: "l"(p), "f"(a), "f"(b), "f"(c), "f"(d) : "memory");
}

__device__ __forceinline__ float warpSum(float v) {
    #pragma unroll
    for (int o = 16; o > 0; o >>= 1) v += __shfl_xor_sync(0xffffffffu, v, o);
    return v;
}

// ---------------- kernels ----------------

// h = gate_emb[gate_types] + qubit_emb[qubit_indices]
__global__ void embed_k(const int* __restrict__ gt, const int* __restrict__ qi,
                        const float* __restrict__ ge, const float* __restrict__ qe, int n) {
    int i = blockIdx.x * blockDim.x + threadIdx.x;
    if (i >= n * (HDIM / 4)) return;
    int node = i >> 5;
    int c = (i & 31) << 2;
    int g = gt[node], q = qi[node];
    float4 a = *(const float4*)(ge + g * HDIM + c);
    float4 b = *(const float4*)(qe + q * HDIM + c);
    float4 r;
    r.x = a.x + b.x; r.y = a.y + b.y; r.z = a.z + b.z; r.w = a.w + b.w;
    *(float4*)(d_h + node * HDIM + c) = r;
}

// --------- CSR build (once per call) ---------
__global__ void csr_zero_k(int n) {
    int i = blockIdx.x * blockDim.x + threadIdx.x;
    if (i < n) { d_deg[i] = 0; d_cur[i] = 0; }
}

__global__ void csr_hist_k(const int* __restrict__ dst, int e) {
    int i = blockIdx.x * blockDim.x + threadIdx.x;
    if (i < e) atomicAdd(&d_deg[dst[i]], 1);
}

// phase 1: per-block (1024 elems) exclusive scan; block total -> d_bsum
__global__ void csr_scan1_k(int n) {
    __shared__ int wsum[32];
    int i = blockIdx.x * 1024 + threadIdx.x;
    int lane = threadIdx.x & 31, wid = threadIdx.x >> 5;
    int v = (i < n) ? d_deg[i] : 0;
    int x = v;
    #pragma unroll
    for (int o = 1; o < 32; o <<= 1) {
        int t = __shfl_up_sync(0xffffffffu, x, o);
        if (lane >= o) x += t;
    }
    if (lane == 31) wsum[wid] = x;
    __syncthreads();
    if (wid == 0) {
        int y = wsum[lane];
        #pragma unroll
        for (int o = 1; o < 32; o <<= 1) {
            int t = __shfl_up_sync(0xffffffffu, y, o);
            if (lane >= o) y += t;
        }
        wsum[lane] = y;
    }
    __syncthreads();
    int base = (wid > 0) ? wsum[wid - 1] : 0;
    if (i < n) d_offs[i] = base + x - v;   // local exclusive prefix
    if (threadIdx.x == 1023) d_bsum[blockIdx.x] = wsum[31];
}

// phase 2: one warp scans <=64 block sums exclusively; writes total to d_offs[n]
__global__ void csr_scan2_k(int nb, int n) {
    int lane = threadIdx.x;  // 32 threads
    int v0 = (lane < nb) ? d_bsum[lane] : 0;
    int v1 = (32 + lane < nb) ? d_bsum[32 + lane] : 0;
    int x0 = v0, x1 = v1;
    #pragma unroll
    for (int o = 1; o < 32; o <<= 1) {
        int t0 = __shfl_up_sync(0xffffffffu, x0, o);
        int t1 = __shfl_up_sync(0xffffffffu, x1, o);
        if (lane >= o) { x0 += t0; x1 += t1; }
    }
    int tot0 = __shfl_sync(0xffffffffu, x0, 31);
    int tot1 = __shfl_sync(0xffffffffu, x1, 31);
    if (lane < nb) d_bbase[lane] = x0 - v0;
    if (32 + lane < nb) d_bbase[32 + lane] = tot0 + x1 - v1;
    if (lane == 0) d_offs[n] = tot0 + tot1;
}

// phase 3: add block bases
__global__ void csr_scan3_k(int n) {
    int i = blockIdx.x * 1024 + threadIdx.x;
    if (i < n) d_offs[i] += d_bbase[blockIdx.x];
}

__global__ void csr_scatter_k(const int* __restrict__ src, const int* __restrict__ dst, int e) {
    int i = blockIdx.x * blockDim.x + threadIdx.x;
    if (i >= e) return;
    int d = dst[i];
    int pos = d_offs[d] + atomicAdd(&d_cur[d], 1);
    d_esrc[pos] = src[i];
}

// feat = h @ W[l].  Block: 64 rows x 128 cols, 256 threads.
// Warp w handles rows w*8..w*8+7; lane handles cols lane*4..lane*4+3.
// A staged transposed in shared: Ast[k][row] (pad 68 keeps float4 alignment).
__global__ void gemm128_k(const float* __restrict__ B, int n) {
    __shared__ float Ast[HDIM][68];
    int row0 = blockIdx.x * 64;
    int tid = threadIdx.x;
    // load A tile transposed: idx -> (r = idx>>7, c = idx&127)
    #pragma unroll
    for (int it = 0; it < 32; it++) {
        int idx = tid + it * 256;
        int r = idx >> 7, c = idx & 127;
        float v = (row0 + r < n) ? d_h[(row0 + r) * HDIM + c] : 0.0f;
        Ast[c][r] = v;
    }
    __syncthreads();
    int wid = tid >> 5, lane = tid & 31;
    int rbase = wid * 8;
    int col = lane * 4;
    float acc[8][4];
    #pragma unroll
    for (int r = 0; r < 8; r++)
        #pragma unroll
        for (int c = 0; c < 4; c++) acc[r][c] = 0.0f;
    #pragma unroll 8
    for (int k = 0; k < HDIM; k++) {
        float4 a0 = *(const float4*)&Ast[k][rbase];       // broadcast within warp
        float4 a1 = *(const float4*)&Ast[k][rbase + 4];
        float4 b = __ldg((const float4*)(B + k * HDIM + col));
        float ar[8] = {a0.x, a0.y, a0.z, a0.w, a1.x, a1.y, a1.z, a1.w};
        #pragma unroll
        for (int r = 0; r < 8; r++) {
            acc[r][0] += ar[r] * b.x;
            acc[r][1] += ar[r] * b.y;
            acc[r][2] += ar[r] * b.z;
            acc[r][3] += ar[r] * b.w;
        }
    }
    #pragma unroll
    for (int r = 0; r < 8; r++) {
        int row = row0 + rbase + r;
        if (row < n) {
            float4 o = make_float4(acc[r][0], acc[r][1], acc[r][2], acc[r][3]);
            *(float4*)(d_feat + row * HDIM + col) = o;
        }
    }
}

// el/er: warp per node, lane covers 4 floats, head = lane>>3, 8-lane segmented reduce
__global__ void attn_k(const float* __restrict__ al, const float* __restrict__ ar, int n) {
    int t = blockIdx.x * blockDim.x + threadIdx.x;
    int node = t >> 5;
    if (node >= n) return;
    int lane = t & 31;
    float4 f = *(const float4*)(d_feat + node * HDIM + lane * 4);
    float4 a = *(const float4*)(al + lane * 4);
    float4 r = *(const float4*)(ar + lane * 4);
    float sl = f.x * a.x + f.y * a.y + f.z * a.z + f.w * a.w;
    float sr = f.x * r.x + f.y * r.y + f.z * r.z + f.w * r.w;
    #pragma unroll
    for (int o = 4; o > 0; o >>= 1) {
        sl += __shfl_xor_sync(0xffffffffu, sl, o);
        sr += __shfl_xor_sync(0xffffffffu, sr, o);
    }
    if ((lane & 7) == 0) {
        int hd = lane >> 3;
        d_el[node * NHEADS + hd] = sl;
        d_er[node * NHEADS + hd] = sr;
    }
}

// Fused per-layer GAT aggregation: warp per dst node.
__global__ void gat_fused_k(const float* __restrict__ bias, int n) {
    int warp = (blockIdx.x * blockDim.x + threadIdx.x) >> 5;
    if (warp >= n) return;
    int lane = threadIdx.x & 31;
    int node = warp;
    int rs = d_offs[node], re = d_offs[node + 1];
    int head = lane >> 3;

    float4 er4 = *(const float4*)(d_er + node * NHEADS);

    // Phase A: per-lane online softmax over strided edges
    float m[4], z[4];
    #pragma unroll
    for (int h = 0; h < 4; h++) { m[h] = -1e30f; z[h] = 0.0f; }
    for (int i = rs + lane; i < re; i += 32) {
        int s = d_esrc[i];
        float4 el4 = *(const float4*)(d_el + s * NHEADS);
        float ev[4] = {el4.x + er4.x, el4.y + er4.y, el4.z + er4.z, el4.w + er4.w};
        #pragma unroll
        for (int h = 0; h < 4; h++) {
            float v = ev[h];
            v = (v > 0.0f) ? v : 0.2f * v;
            float nm = fmaxf(m[h], v);
            z[h] = z[h] * __expf(m[h] - nm) + __expf(v - nm);
            m[h] = nm;
        }
    }
    #pragma unroll
    for (int o = 16; o > 0; o >>= 1) {
        #pragma unroll
        for (int h = 0; h < 4; h++) {
            float om = __shfl_xor_sync(0xffffffffu, m[h], o);
            float oz = __shfl_xor_sync(0xffffffffu, z[h], o);
            float nm = fmaxf(m[h], om);
            z[h] = z[h] * __expf(m[h] - nm) + oz * __expf(om - nm);
            m[h] = nm;
        }
    }
    float erh[4] = {er4.x, er4.y, er4.z, er4.w};
    float m_h = m[head];
    float zq = z[head];
    float rz_h = (zq > 0.0f) ? (1.0f / zq) : 0.0f;
    float er_h = erh[head];

    // Phase B: joint loop over edges, lane owns 4 feature channels
    float4 acc = make_float4(0.0f, 0.0f, 0.0f, 0.0f);
    for (int i = rs; i < re; i++) {
        int s = d_esrc[i];
        float el_h = d_el[s * NHEADS + head];
        float v = el_h + er_h;
        v = (v > 0.0f) ? v : 0.2f * v;
        float a = __expf(v - m_h) * rz_h;
        float4 f = *(const float4*)(d_feat + s * HDIM + lane * 4);
        acc.x += a * f.x; acc.y += a * f.y; acc.z += a * f.z; acc.w += a * f.w;
    }

    float4 hv = *(const float4*)(d_h + node * HDIM + lane * 4);
    float4 bv = *(const float4*)(bias + lane * 4);
    float4 y;
    y.x = fmaxf(acc.x + hv.x + bv.x, 0.0f);
    y.y = fmaxf(acc.y + hv.y + bv.y, 0.0f);
    y.z = fmaxf(acc.z + hv.z + bv.z, 0.0f);
    y.w = fmaxf(acc.w + hv.w + bv.w, 0.0f);
    *(float4*)(d_h + node * HDIM + lane * 4) = y;
}

// Fused LayerNorm + gate projection + per-graph gate max. Warp per node, in-place on d_h.
__global__ void ln_gate_k(const float* __restrict__ gamma, const float* __restrict__ beta,
                          const float* __restrict__ gw, const float* __restrict__ gb,
                          const int* __restrict__ gid, int n) {
    int t = blockIdx.x * blockDim.x + threadIdx.x;
    int node = t >> 5;
    if (node >= n) return;
    int lane = t & 31;
    float4 x = *(const float4*)(d_h + node * HDIM + lane * 4);
    float s = x.x + x.y + x.z + x.w;
    float sq = x.x * x.x + x.y * x.y + x.z * x.z + x.w * x.w;
    s = warpSum(s);
    sq = warpSum(sq);
    float mu = s * (1.0f / HDIM);
    float var = sq * (1.0f / HDIM) - mu * mu;
    float inv = rsqrtf(var + 1e-5f);
    float4 g = *(const float4*)(gamma + lane * 4);
    float4 b = *(const float4*)(beta + lane * 4);
    float4 y;
    y.x = (x.x - mu) * inv * g.x + b.x;
    y.y = (x.y - mu) * inv * g.y + b.y;
    y.z = (x.z - mu) * inv * g.z + b.z;
    y.w = (x.w - mu) * inv * g.w + b.w;
    *(float4*)(d_h + node * HDIM + lane * 4) = y;
    float4 w = *(const float4*)(gw + lane * 4);
    float gp = y.x * w.x + y.y * w.y + y.z * w.z + y.w * w.w;
    gp = warpSum(gp);
    if (lane == 0) {
        float gv = gp + gb[0];
        d_gate[node] = gv;
        atomicMaxFloat(&d_gmax[gid[node]], gv);
    }
}

__global__ void pool_init_k() {
    int i = blockIdx.x * blockDim.x + threadIdx.x;
    if (i < GMAX * HDIM) d_zg[i] = 0.0f;
    if (i < GMAX) { d_gmax[i] = -INFINITY; d_gz[i] = 0.0f; }
}

// pool: p = exp(gate - gmax); gz += p; zg += p*h. One warp per node.
__global__ void pool_k(const int* __restrict__ gid, int n) {
    int t = blockIdx.x * blockDim.x + threadIdx.x;
    int node = t >> 5;
    if (node >= n) return;
    int lane = t & 31;
    int g = gid[node];
    float p = __expf(d_gate[node] - d_gmax[g]);
    if (lane == 0) atomicAdd(&d_gz[g], p);
    float4 x = *(const float4*)(d_h + node * HDIM + lane * 4);
    redAdd4(d_zg + g * HDIM + lane * 4, x.x * p, x.y * p, x.z * p, x.w * p);
}

// z1 = relu((zg/gz) @ proj_w1 + b1)
__global__ void final1_k(const float* __restrict__ W1, const float* __restrict__ b1) {
    __shared__ float row[HDIM];
    int g = blockIdx.x;
    int t = threadIdx.x;
    float gz = d_gz[g];
    float inv = (gz > 0.0f) ? (1.0f / gz) : 0.0f;
    row[t] = d_zg[g * HDIM + t] * inv;
    __syncthreads();
    float acc = b1[t];
    #pragma unroll 8
    for (int k = 0; k < HDIM; k++) acc += row[k] * W1[k * HDIM + t];
    d_z1[g * HDIM + t] = (acc > 0.0f) ? acc : 0.0f;
}

// out = z1 @ proj_w2 + b2
__global__ void final2_k(const float* __restrict__ W2, const float* __restrict__ b2,
                         float* __restrict__ out) {
    __shared__ float row[HDIM];
    int g = blockIdx.x;
    int t = threadIdx.x;
    row[t] = d_z1[g * HDIM + t];
    row[t + 64] = d_z1[g * HDIM + t + 64];
    __syncthreads();
    float acc = b2[t];
    #pragma unroll 8
    for (int k = 0; k < HDIM; k++) acc += row[k] * W2[k * 64 + t];
    out[g * 64 + t] = acc;
}

// ---------------- launch ----------------
extern "C" void kernel_launch(void* const* d_in, const int* in_sizes, int n_in,
                              void* d_out, int out_size) {
    const int*   gt    = (const int*)d_in[0];
    const int*   qi    = (const int*)d_in[1];
    const int*   src   = (const int*)d_in[2];
    const int*   dst   = (const int*)d_in[3];
    const int*   gid   = (const int*)d_in[4];
    const float* ge    = (const float*)d_in[5];
    const float* qe    = (const float*)d_in[6];
    const float* W     = (const float*)d_in[7];
    const float* al    = (const float*)d_in[8];
    const float* ar    = (const float*)d_in[9];
    const float* bias  = (const float*)d_in[10];
    const float* gamma = (const float*)d_in[11];
    const float* beta  = (const float*)d_in[12];
    const float* gw    = (const float*)d_in[13];
    const float* gb    = (const float*)d_in[14];
    const float* W1    = (const float*)d_in[15];
    const float* b1    = (const float*)d_in[16];
    const float* W2    = (const float*)d_in[17];
    const float* b2    = (const float*)d_in[18];

    int n = in_sizes[0];
    int e = in_sizes[2];

    const int T = 256;
    int gEmbed = (n * (HDIM / 4) + T - 1) / T;
    int gGemm  = (n + 63) / 64;
    int gWarpN = (n * 32 + T - 1) / T;   // one warp per node
    int gEdge  = (e + T - 1) / T;
    int gNode  = (n + T - 1) / T;
    int nb     = (n + 1023) / 1024;

    embed_k<<<gEmbed, T>>>(gt, qi, ge, qe, n);

    // CSR build (once per call)
    csr_zero_k<<<gNode, T>>>(n);
    csr_hist_k<<<gEdge, T>>>(dst, e);
    csr_scan1_k<<<nb, 1024>>>(n);
    csr_scan2_k<<<1, 32>>>(nb, n);
    csr_scan3_k<<<nb, 1024>>>(n);
    csr_scatter_k<<<gEdge, T>>>(src, dst, e);

    for (int l = 0; l < 3; l++) {
        gemm128_k<<<gGemm, 256>>>(W + l * HDIM * HDIM, n);
        attn_k<<<gWarpN, T>>>(al + l * HDIM, ar + l * HDIM, n);
        gat_fused_k<<<gWarpN, T>>>(bias + l * HDIM, n);
    }

    pool_init_k<<<(GMAX * HDIM + T - 1) / T, T>>>();
    ln_gate_k<<<gWarpN, T>>>(gamma, beta, gw, gb, gid, n);
    pool_k<<<gWarpN, T>>>(gid, n);
    final1_k<<<GMAX, HDIM>>>(W1, b1);
    final2_k<<<GMAX, 64>>>(W2, b2, (float*)d_out);
}

// round 5
// speedup vs baseline: 1.9488x; 1.1064x over previous
#include <cuda_runtime.h>
#include <math.h>

#define NMAX 50000
#define EMAX 600000
#define HDIM 128
#define NHEADS 4
#define GMAX 64

// ---------------- scratch (device globals; no allocation) ----------------
__device__ float d_h[NMAX * HDIM];
__device__ float d_feat[NMAX * HDIM];
__device__ float d_el[NMAX * NHEADS];
__device__ float d_er[NMAX * NHEADS];
__device__ int   d_deg[NMAX];
__device__ int   d_cur[NMAX];
__device__ int   d_offs[NMAX + 1];
__device__ int   d_esrc[EMAX];
__device__ int   d_bsum[64];
__device__ int   d_bbase[64];
__device__ float d_gate[NMAX];
__device__ float d_gmax[GMAX];
__device__ float d_gz[GMAX];
__device__ float d_zg[GMAX * HDIM];
__device__ float d_z1[GMAX * HDIM];

// ---------------- helpers ----------------
__device__ __forceinline__ void atomicMaxFloat(float* addr, float v) {
    if (v >= 0.0f) atomicMax((int*)addr, __float_as_int(v));
    else           atomicMin((unsigned int*)addr, __float_as_uint(v));
}

__device__ __forceinline__ void redAdd4(float* p, float a, float b, float c, float d) {
    asm volatile("red.global.add.v4.f32 [%0], {%1, %2, %3, %4};"
                 :: "l"(p), "f"(a), "f"(b), "f"(c), "f"(d) : "memory");
}

__device__ __forceinline__ float warpSum(float v) {
    #pragma unroll
    for (int o = 16; o > 0; o >>= 1) v += __shfl_xor_sync(0xffffffffu, v, o);
    return v;
}

// ---------------- kernels ----------------

// h = gate_emb[gate_types] + qubit_emb[qubit_indices]
__global__ void embed_k(const int* __restrict__ gt, const int* __restrict__ qi,
                        const float* __restrict__ ge, const float* __restrict__ qe, int n) {
    int i = blockIdx.x * blockDim.x + threadIdx.x;
    if (i >= n * (HDIM / 4)) return;
    int node = i >> 5;
    int c = (i & 31) << 2;
    int g = gt[node], q = qi[node];
    float4 a = *(const float4*)(ge + g * HDIM + c);
    float4 b = *(const float4*)(qe + q * HDIM + c);
    float4 r;
    r.x = a.x + b.x; r.y = a.y + b.y; r.z = a.z + b.z; r.w = a.w + b.w;
    *(float4*)(d_h + node * HDIM + c) = r;
}

// --------- CSR build (once per call) ---------
__global__ void csr_zero_k(int n) {
    int i = blockIdx.x * blockDim.x + threadIdx.x;
    if (i < n) { d_deg[i] = 0; d_cur[i] = 0; }
}

__global__ void csr_hist_k(const int* __restrict__ dst, int e) {
    int i = blockIdx.x * blockDim.x + threadIdx.x;
    if (i < e) atomicAdd(&d_deg[dst[i]], 1);
}

// phase 1: per-block (1024 elems) exclusive scan; block total -> d_bsum
__global__ void csr_scan1_k(int n) {
    __shared__ int wsum[32];
    int i = blockIdx.x * 1024 + threadIdx.x;
    int lane = threadIdx.x & 31, wid = threadIdx.x >> 5;
    int v = (i < n) ? d_deg[i] : 0;
    int x = v;
    #pragma unroll
    for (int o = 1; o < 32; o <<= 1) {
        int t = __shfl_up_sync(0xffffffffu, x, o);
        if (lane >= o) x += t;
    }
    if (lane == 31) wsum[wid] = x;
    __syncthreads();
    if (wid == 0) {
        int y = wsum[lane];
        #pragma unroll
        for (int o = 1; o < 32; o <<= 1) {
            int t = __shfl_up_sync(0xffffffffu, y, o);
            if (lane >= o) y += t;
        }
        wsum[lane] = y;
    }
    __syncthreads();
    int base = (wid > 0) ? wsum[wid - 1] : 0;
    if (i < n) d_offs[i] = base + x - v;
    if (threadIdx.x == 1023) d_bsum[blockIdx.x] = wsum[31];
}

// phase 2: one warp scans <=64 block sums exclusively; writes total to d_offs[n]
__global__ void csr_scan2_k(int nb, int n) {
    int lane = threadIdx.x;
    int v0 = (lane < nb) ? d_bsum[lane] : 0;
    int v1 = (32 + lane < nb) ? d_bsum[32 + lane] : 0;
    int x0 = v0, x1 = v1;
    #pragma unroll
    for (int o = 1; o < 32; o <<= 1) {
        int t0 = __shfl_up_sync(0xffffffffu, x0, o);
        int t1 = __shfl_up_sync(0xffffffffu, x1, o);
        if (lane >= o) { x0 += t0; x1 += t1; }
    }
    int tot0 = __shfl_sync(0xffffffffu, x0, 31);
    int tot1 = __shfl_sync(0xffffffffu, x1, 31);
    if (lane < nb) d_bbase[lane] = x0 - v0;
    if (32 + lane < nb) d_bbase[32 + lane] = tot0 + x1 - v1;
    if (lane == 0) d_offs[n] = tot0 + tot1;
}

// phase 3: add block bases
__global__ void csr_scan3_k(int n) {
    int i = blockIdx.x * 1024 + threadIdx.x;
    if (i < n) d_offs[i] += d_bbase[blockIdx.x];
}

__global__ void csr_scatter_k(const int* __restrict__ src, const int* __restrict__ dst, int e) {
    int i = blockIdx.x * blockDim.x + threadIdx.x;
    if (i >= e) return;
    int d = dst[i];
    int pos = d_offs[d] + atomicAdd(&d_cur[d], 1);
    d_esrc[pos] = src[i];
}

// feat = h @ W[l] with fused attn epilogue (el/er from accumulator registers).
// Block: 64 rows x 128 cols, 256 threads. Warp w: rows w*8..w*8+7; lane: cols lane*4..+3.
__global__ void gemm_attn_k(const float* __restrict__ B,
                            const float* __restrict__ al, const float* __restrict__ ar, int n) {
    __shared__ float Ast[HDIM][68];
    int row0 = blockIdx.x * 64;
    int tid = threadIdx.x;
    #pragma unroll
    for (int it = 0; it < 32; it++) {
        int idx = tid + it * 256;
        int r = idx >> 7, c = idx & 127;
        float v = (row0 + r < n) ? d_h[(row0 + r) * HDIM + c] : 0.0f;
        Ast[c][r] = v;
    }
    __syncthreads();
    int wid = tid >> 5, lane = tid & 31;
    int rbase = wid * 8;
    int col = lane * 4;
    int head = lane >> 3;
    float acc[8][4];
    #pragma unroll
    for (int r = 0; r < 8; r++)
        #pragma unroll
        for (int c = 0; c < 4; c++) acc[r][c] = 0.0f;
    #pragma unroll 8
    for (int k = 0; k < HDIM; k++) {
        float4 a0 = *(const float4*)&Ast[k][rbase];
        float4 a1 = *(const float4*)&Ast[k][rbase + 4];
        float4 b = __ldg((const float4*)(B + k * HDIM + col));
        float arr[8] = {a0.x, a0.y, a0.z, a0.w, a1.x, a1.y, a1.z, a1.w};
        #pragma unroll
        for (int r = 0; r < 8; r++) {
            acc[r][0] += arr[r] * b.x;
            acc[r][1] += arr[r] * b.y;
            acc[r][2] += arr[r] * b.z;
            acc[r][3] += arr[r] * b.w;
        }
    }
    float4 av = __ldg((const float4*)(al + col));
    float4 rv = __ldg((const float4*)(ar + col));
    #pragma unroll
    for (int r = 0; r < 8; r++) {
        int row = row0 + rbase + r;
        if (row < n) {
            float4 o = make_float4(acc[r][0], acc[r][1], acc[r][2], acc[r][3]);
            *(float4*)(d_feat + row * HDIM + col) = o;
        }
        float sl = acc[r][0] * av.x + acc[r][1] * av.y + acc[r][2] * av.z + acc[r][3] * av.w;
        float sr = acc[r][0] * rv.x + acc[r][1] * rv.y + acc[r][2] * rv.z + acc[r][3] * rv.w;
        #pragma unroll
        for (int o = 4; o > 0; o >>= 1) {
            sl += __shfl_xor_sync(0xffffffffu, sl, o);
            sr += __shfl_xor_sync(0xffffffffu, sr, o);
        }
        if ((lane & 7) == 0) {
            int row2 = row0 + rbase + r;
            if (row2 < n) {
                d_el[row2 * NHEADS + head] = sl;
                d_er[row2 * NHEADS + head] = sr;
            }
        }
    }
}

// Fused per-layer GAT aggregation: warp per dst node.
// Phase A: per-head max only (no exp). Phase B: chunked — compute a once/edge,
// park in shared, accumulate z in regs; gather feat; normalize in epilogue.
__global__ void gat_fused_k(const float* __restrict__ bias, int n) {
    __shared__ float sh_a[8][128];   // per warp: 32 edges x 4 heads
    int warp = (blockIdx.x * blockDim.x + threadIdx.x) >> 5;
    if (warp >= n) return;
    int w = threadIdx.x >> 5;
    int lane = threadIdx.x & 31;
    int node = warp;
    int rs = d_offs[node], re = d_offs[node + 1];
    int head = lane >> 3;

    float4 er4 = *(const float4*)(d_er + node * NHEADS);

    // Phase A: per-head max over edges
    float m[4] = {-1e30f, -1e30f, -1e30f, -1e30f};
    for (int i = rs + lane; i < re; i += 32) {
        int s = d_esrc[i];
        float4 el4 = *(const float4*)(d_el + s * NHEADS);
        float v0 = el4.x + er4.x; v0 = (v0 > 0.0f) ? v0 : 0.2f * v0;
        float v1 = el4.y + er4.y; v1 = (v1 > 0.0f) ? v1 : 0.2f * v1;
        float v2 = el4.z + er4.z; v2 = (v2 > 0.0f) ? v2 : 0.2f * v2;
        float v3 = el4.w + er4.w; v3 = (v3 > 0.0f) ? v3 : 0.2f * v3;
        m[0] = fmaxf(m[0], v0); m[1] = fmaxf(m[1], v1);
        m[2] = fmaxf(m[2], v2); m[3] = fmaxf(m[3], v3);
    }
    #pragma unroll
    for (int o = 16; o > 0; o >>= 1) {
        #pragma unroll
        for (int h = 0; h < 4; h++)
            m[h] = fmaxf(m[h], __shfl_xor_sync(0xffffffffu, m[h], o));
    }

    // Phase B
    float4 zacc = make_float4(0.0f, 0.0f, 0.0f, 0.0f);
    float4 acc = make_float4(0.0f, 0.0f, 0.0f, 0.0f);
    for (int base = rs; base < re; base += 32) {
        int i = base + lane;
        int s_reg = 0;
        float4 a4 = make_float4(0.0f, 0.0f, 0.0f, 0.0f);
        if (i < re) {
            s_reg = d_esrc[i];
            float4 el4 = *(const float4*)(d_el + s_reg * NHEADS);
            float v0 = el4.x + er4.x; v0 = (v0 > 0.0f) ? v0 : 0.2f * v0;
            float v1 = el4.y + er4.y; v1 = (v1 > 0.0f) ? v1 : 0.2f * v1;
            float v2 = el4.z + er4.z; v2 = (v2 > 0.0f) ? v2 : 0.2f * v2;
            float v3 = el4.w + er4.w; v3 = (v3 > 0.0f) ? v3 : 0.2f * v3;
            a4.x = __expf(v0 - m[0]); a4.y = __expf(v1 - m[1]);
            a4.z = __expf(v2 - m[2]); a4.w = __expf(v3 - m[3]);
            zacc.x += a4.x; zacc.y += a4.y; zacc.z += a4.z; zacc.w += a4.w;
        }
        *(float4*)&sh_a[w][lane * 4] = a4;
        __syncwarp();
        int cnt = min(32, re - base);
        for (int j = 0; j < cnt; j++) {
            int s = __shfl_sync(0xffffffffu, s_reg, j);
            float a = sh_a[w][j * 4 + head];
            float4 f = *(const float4*)(d_feat + s * HDIM + lane * 4);
            acc.x += a * f.x; acc.y += a * f.y; acc.z += a * f.z; acc.w += a * f.w;
        }
        __syncwarp();
    }
    // reduce z across warp
    #pragma unroll
    for (int o = 16; o > 0; o >>= 1) {
        zacc.x += __shfl_xor_sync(0xffffffffu, zacc.x, o);
        zacc.y += __shfl_xor_sync(0xffffffffu, zacc.y, o);
        zacc.z += __shfl_xor_sync(0xffffffffu, zacc.z, o);
        zacc.w += __shfl_xor_sync(0xffffffffu, zacc.w, o);
    }
    float zh[4] = {zacc.x, zacc.y, zacc.z, zacc.w};
    float zq = zh[head];
    float rz = (zq > 0.0f) ? (1.0f / zq) : 0.0f;

    float4 hv = *(const float4*)(d_h + node * HDIM + lane * 4);
    float4 bv = *(const float4*)(bias + lane * 4);
    float4 y;
    y.x = fmaxf(acc.x * rz + hv.x + bv.x, 0.0f);
    y.y = fmaxf(acc.y * rz + hv.y + bv.y, 0.0f);
    y.z = fmaxf(acc.z * rz + hv.z + bv.z, 0.0f);
    y.w = fmaxf(acc.w * rz + hv.w + bv.w, 0.0f);
    *(float4*)(d_h + node * HDIM + lane * 4) = y;
}

// Fused LayerNorm + gate projection + per-graph gate max.
__global__ void ln_gate_k(const float* __restrict__ gamma, const float* __restrict__ beta,
                          const float* __restrict__ gw, const float* __restrict__ gb,
                          const int* __restrict__ gid, int n) {
    int t = blockIdx.x * blockDim.x + threadIdx.x;
    int node = t >> 5;
    if (node >= n) return;
    int lane = t & 31;
    float4 x = *(const float4*)(d_h + node * HDIM + lane * 4);
    float s = x.x + x.y + x.z + x.w;
    float sq = x.x * x.x + x.y * x.y + x.z * x.z + x.w * x.w;
    s = warpSum(s);
    sq = warpSum(sq);
    float mu = s * (1.0f / HDIM);
    float var = sq * (1.0f / HDIM) - mu * mu;
    float inv = rsqrtf(var + 1e-5f);
    float4 g = *(const float4*)(gamma + lane * 4);
    float4 b = *(const float4*)(beta + lane * 4);
    float4 y;
    y.x = (x.x - mu) * inv * g.x + b.x;
    y.y = (x.y - mu) * inv * g.y + b.y;
    y.z = (x.z - mu) * inv * g.z + b.z;
    y.w = (x.w - mu) * inv * g.w + b.w;
    *(float4*)(d_h + node * HDIM + lane * 4) = y;
    float4 w = *(const float4*)(gw + lane * 4);
    float gp = y.x * w.x + y.y * w.y + y.z * w.z + y.w * w.w;
    gp = warpSum(gp);
    if (lane == 0) {
        float gv = gp + gb[0];
        d_gate[node] = gv;
        atomicMaxFloat(&d_gmax[gid[node]], gv);
    }
}

__global__ void pool_init_k() {
    int i = blockIdx.x * blockDim.x + threadIdx.x;
    if (i < GMAX * HDIM) d_zg[i] = 0.0f;
    if (i < GMAX) { d_gmax[i] = -INFINITY; d_gz[i] = 0.0f; }
}

// pool: p = exp(gate - gmax); gz += p; zg += p*h. One warp per node.
__global__ void pool_k(const int* __restrict__ gid, int n) {
    int t = blockIdx.x * blockDim.x + threadIdx.x;
    int node = t >> 5;
    if (node >= n) return;
    int lane = t & 31;
    int g = gid[node];
    float p = __expf(d_gate[node] - d_gmax[g]);
    if (lane == 0) atomicAdd(&d_gz[g], p);
    float4 x = *(const float4*)(d_h + node * HDIM + lane * 4);
    redAdd4(d_zg + g * HDIM + lane * 4, x.x * p, x.y * p, x.z * p, x.w * p);
}

// z1 = relu((zg/gz) @ proj_w1 + b1)
__global__ void final1_k(const float* __restrict__ W1, const float* __restrict__ b1) {
    __shared__ float row[HDIM];
    int g = blockIdx.x;
    int t = threadIdx.x;
    float gz = d_gz[g];
    float inv = (gz > 0.0f) ? (1.0f / gz) : 0.0f;
    row[t] = d_zg[g * HDIM + t] * inv;
    __syncthreads();
    float acc = b1[t];
    #pragma unroll 8
    for (int k = 0; k < HDIM; k++) acc += row[k] * W1[k * HDIM + t];
    d_z1[g * HDIM + t] = (acc > 0.0f) ? acc : 0.0f;
}

// out = z1 @ proj_w2 + b2
__global__ void final2_k(const float* __restrict__ W2, const float* __restrict__ b2,
                         float* __restrict__ out) {
    __shared__ float row[HDIM];
    int g = blockIdx.x;
    int t = threadIdx.x;
    row[t] = d_z1[g * HDIM + t];
    row[t + 64] = d_z1[g * HDIM + t + 64];
    __syncthreads();
    float acc = b2[t];
    #pragma unroll 8
    for (int k = 0; k < HDIM; k++) acc += row[k] * W2[k * 64 + t];
    out[g * 64 + t] = acc;
}

// ---------------- launch ----------------
extern "C" void kernel_launch(void* const* d_in, const int* in_sizes, int n_in,
                              void* d_out, int out_size) {
    const int*   gt    = (const int*)d_in[0];
    const int*   qi    = (const int*)d_in[1];
    const int*   src   = (const int*)d_in[2];
    const int*   dst   = (const int*)d_in[3];
    const int*   gid   = (const int*)d_in[4];
    const float* ge    = (const float*)d_in[5];
    const float* qe    = (const float*)d_in[6];
    const float* W     = (const float*)d_in[7];
    const float* al    = (const float*)d_in[8];
    const float* ar    = (const float*)d_in[9];
    const float* bias  = (const float*)d_in[10];
    const float* gamma = (const float*)d_in[11];
    const float* beta  = (const float*)d_in[12];
    const float* gw    = (const float*)d_in[13];
    const float* gb    = (const float*)d_in[14];
    const float* W1    = (const float*)d_in[15];
    const float* b1    = (const float*)d_in[16];
    const float* W2    = (const float*)d_in[17];
    const float* b2    = (const float*)d_in[18];

    int n = in_sizes[0];
    int e = in_sizes[2];

    const int T = 256;
    int gEmbed = (n * (HDIM / 4) + T - 1) / T;
    int gGemm  = (n + 63) / 64;
    int gWarpN = (n * 32 + T - 1) / T;
    int gEdge  = (e + T - 1) / T;
    int gNode  = (n + T - 1) / T;
    int nb     = (n + 1023) / 1024;

    embed_k<<<gEmbed, T>>>(gt, qi, ge, qe, n);

    csr_zero_k<<<gNode, T>>>(n);
    csr_hist_k<<<gEdge, T>>>(dst, e);
    csr_scan1_k<<<nb, 1024>>>(n);
    csr_scan2_k<<<1, 32>>>(nb, n);
    csr_scan3_k<<<nb, 1024>>>(n);
    csr_scatter_k<<<gEdge, T>>>(src, dst, e);

    for (int l = 0; l < 3; l++) {
        gemm_attn_k<<<gGemm, 256>>>(W + l * HDIM * HDIM, al + l * HDIM, ar + l * HDIM, n);
        gat_fused_k<<<gWarpN, T>>>(bias + l * HDIM, n);
    }

    pool_init_k<<<(GMAX * HDIM + T - 1) / T, T>>>();
    ln_gate_k<<<gWarpN, T>>>(gamma, beta, gw, gb, gid, n);
    pool_k<<<gWarpN, T>>>(gid, n);
    final1_k<<<GMAX, HDIM>>>(W1, b1);
    final2_k<<<GMAX, 64>>>(W2, b2, (float*)d_out);
}